// round 1
// baseline (speedup 1.0000x reference)
#include <cuda_runtime.h>

#define N_NODES 100000
#define N_EDGES 1600000
#define IN_DIM  128
#define HID     64

// ---- scratch (static device globals; no runtime allocation) ----
__device__ float g_y[(size_t)N_NODES * HID];     // (x@W)*norm_out, reused both layers
__device__ float g_agg[(size_t)N_NODES * HID];   // scatter-add destination
__device__ float g_h[(size_t)N_NODES * HID];     // layer-1 activation
__device__ float g_Hs[(size_t)N_NODES * HID];    // h2 @ W3[0:64]  + b3
__device__ float g_Hd[(size_t)N_NODES * HID];    // h2 @ W3[64:128]
__device__ float g_norm_out[N_NODES];
__device__ float g_norm_in[N_NODES];
__device__ int   g_deg_out[N_NODES];
__device__ int   g_deg_in[N_NODES];

// ---- 0: zero agg + degree counters ----
__global__ void k_zero() {
    int i = blockIdx.x * blockDim.x + threadIdx.x;
    const int tot4 = N_NODES * HID / 4;
    if (i < tot4) ((float4*)g_agg)[i] = make_float4(0.f, 0.f, 0.f, 0.f);
    if (i < N_NODES) { g_deg_out[i] = 0; g_deg_in[i] = 0; }
}

// ---- 1: degree histogram (last-timestep edges only) ----
__global__ void k_deg(const int* __restrict__ src, const int* __restrict__ dst) {
    int i = blockIdx.x * blockDim.x + threadIdx.x;
    if (i < N_EDGES) {
        atomicAdd(&g_deg_out[src[i]], 1);
        atomicAdd(&g_deg_in[dst[i]], 1);
    }
}

// ---- 2: symmetric-norm factors ----
__global__ void k_norm() {
    int i = blockIdx.x * blockDim.x + threadIdx.x;
    if (i < N_NODES) {
        g_norm_out[i] = rsqrtf(fmaxf((float)g_deg_out[i], 1.f));
        g_norm_in[i]  = rsqrtf(fmaxf((float)g_deg_in[i],  1.f));
    }
}

// ---- 3: y = (x @ W1) * norm_out   (x: [N,128], W1: [128,64]) ----
__global__ __launch_bounds__(256) void k_gemm1(const float* __restrict__ x,
                                               const float* __restrict__ W1) {
    __shared__ float Ws[IN_DIM * HID];   // 32 KB
    __shared__ float xs[4][IN_DIM];
    for (int i = threadIdx.x; i < IN_DIM * HID; i += blockDim.x) Ws[i] = W1[i];
    const int ln  = threadIdx.x >> 6;   // node slot 0..3
    const int col = threadIdx.x & 63;
    for (int v0 = blockIdx.x * 4; v0 < N_NODES; v0 += gridDim.x * 4) {
        __syncthreads();
        for (int i = threadIdx.x; i < 4 * IN_DIM; i += blockDim.x) {
            int vv = v0 + (i >> 7);
            xs[i >> 7][i & 127] = (vv < N_NODES) ? x[(size_t)vv * IN_DIM + (i & 127)] : 0.f;
        }
        __syncthreads();
        int v = v0 + ln;
        if (v < N_NODES) {
            float acc = 0.f;
            #pragma unroll
            for (int k = 0; k < IN_DIM; k++)
                acc = fmaf(xs[ln][k], Ws[k * HID + col], acc);
            g_y[(size_t)v * HID + col] = acc * g_norm_out[v];
        }
    }
}

// ---- 4/7: agg[dst] += y[src]  (16 threads per edge, vectorized float4 atomics) ----
__global__ __launch_bounds__(256) void k_scatter(const int* __restrict__ src,
                                                 const int* __restrict__ dst) {
    long long tid = (long long)blockIdx.x * blockDim.x + threadIdx.x;
    int e = (int)(tid >> 4);
    if (e >= N_EDGES) return;
    int q = ((int)tid & 15) * 4;
    int s = __ldg(&src[e]);
    int d = __ldg(&dst[e]);
    float4 v = *(const float4*)(g_y + (size_t)s * HID + q);
    atomicAdd((float4*)(g_agg + (size_t)d * HID + q), v);
}

// ---- 5: h = relu(agg*norm_in + b1); agg = 0 (for layer-2 reuse) ----
__global__ void k_relu_b1(const float* __restrict__ b1) {
    int i = blockIdx.x * blockDim.x + threadIdx.x;
    if (i < N_NODES * HID) {
        int v = i >> 6, j = i & 63;
        float val = g_agg[i] * g_norm_in[v] + b1[j];
        g_h[i] = fmaxf(val, 0.f);
        g_agg[i] = 0.f;
    }
}

// ---- 6: y = (h @ W2) * norm_out   (h: [N,64], W2: [64,64]) ----
__global__ __launch_bounds__(256) void k_gemm2(const float* __restrict__ W2) {
    __shared__ float Ws[HID * HID];     // 16 KB
    __shared__ float hs[4][HID];
    for (int i = threadIdx.x; i < HID * HID; i += blockDim.x) Ws[i] = W2[i];
    const int ln  = threadIdx.x >> 6;
    const int col = threadIdx.x & 63;
    for (int v0 = blockIdx.x * 4; v0 < N_NODES; v0 += gridDim.x * 4) {
        int v = v0 + ln;
        __syncthreads();
        hs[ln][col] = (v < N_NODES) ? g_h[(size_t)v * HID + col] : 0.f;
        __syncthreads();
        if (v < N_NODES) {
            float acc = 0.f;
            #pragma unroll
            for (int k = 0; k < HID; k++)
                acc = fmaf(hs[ln][k], Ws[k * HID + col], acc);
            g_y[(size_t)v * HID + col] = acc * g_norm_out[v];
        }
    }
}

// ---- 8: h2 = agg*norm_in + b2; Hs = h2@W3[0:64] + b3; Hd = h2@W3[64:128] ----
__global__ __launch_bounds__(256) void k_layer2_post(const float* __restrict__ W3,
                                                     const float* __restrict__ b2v,
                                                     const float* __restrict__ b3v) {
    __shared__ float Ws[2 * HID * HID];  // 32 KB
    __shared__ float h2s[4][HID];
    for (int i = threadIdx.x; i < 2 * HID * HID; i += blockDim.x) Ws[i] = W3[i];
    const int ln  = threadIdx.x >> 6;
    const int col = threadIdx.x & 63;
    const float b2c = b2v[col];
    const float b3c = b3v[col];
    for (int v0 = blockIdx.x * 4; v0 < N_NODES; v0 += gridDim.x * 4) {
        int v = v0 + ln;
        __syncthreads();
        if (v < N_NODES)
            h2s[ln][col] = g_agg[(size_t)v * HID + col] * g_norm_in[v] + b2c;
        __syncthreads();
        if (v < N_NODES) {
            float as = b3c, ad = 0.f;
            #pragma unroll
            for (int k = 0; k < HID; k++) {
                float hk = h2s[ln][k];
                as = fmaf(hk, Ws[k * HID + col], as);
                ad = fmaf(hk, Ws[(HID + k) * HID + col], ad);
            }
            g_Hs[(size_t)v * HID + col] = as;
            g_Hd[(size_t)v * HID + col] = ad;
        }
    }
}

// ---- 9: per-edge score (one warp per edge) ----
__global__ __launch_bounds__(256) void k_score(const int* __restrict__ sn,
                                               const int* __restrict__ dn,
                                               const float* __restrict__ W4,
                                               const float* __restrict__ b4,
                                               float* __restrict__ out) {
    int warp = (blockIdx.x * blockDim.x + threadIdx.x) >> 5;
    int lane = threadIdx.x & 31;
    if (warp >= N_EDGES) return;
    int s = __ldg(&sn[warp]);
    int d = __ldg(&dn[warp]);
    const float* hs = g_Hs + (size_t)s * HID;
    const float* hd = g_Hd + (size_t)d * HID;
    float a0 = fmaxf(hs[lane]      + hd[lane],      0.f);
    float a1 = fmaxf(hs[lane + 32] + hd[lane + 32], 0.f);
    float p  = a0 * __ldg(&W4[lane]) + a1 * __ldg(&W4[lane + 32]);
    #pragma unroll
    for (int o = 16; o; o >>= 1) p += __shfl_down_sync(0xffffffffu, p, o);
    if (lane == 0) out[warp] = p + __ldg(&b4[0]);
}

extern "C" void kernel_launch(void* const* d_in, const int* in_sizes, int n_in,
                              void* d_out, int out_size) {
    const float* feats    = (const float*)d_in[0];
    const float* W1       = (const float*)d_in[1];
    const float* b1       = (const float*)d_in[2];
    const float* W2       = (const float*)d_in[3];
    const float* b2       = (const float*)d_in[4];
    const float* W3       = (const float*)d_in[5];
    const float* b3       = (const float*)d_in[6];
    const float* W4       = (const float*)d_in[7];
    const float* b4       = (const float*)d_in[8];
    const int*   src_seq  = (const int*)d_in[9];
    const int*   dst_seq  = (const int*)d_in[10];
    const int*   src_next = (const int*)d_in[11];
    const int*   dst_next = (const int*)d_in[12];
    float* out = (float*)d_out;

    // use_temporal=False in the reference: only snapshot t = T-1 = 2 contributes.
    const float* x_last = feats   + (size_t)2 * N_NODES * IN_DIM;
    const int*   src    = src_seq + (size_t)2 * N_EDGES;
    const int*   dst    = dst_seq + (size_t)2 * N_EDGES;

    const int zero_n = N_NODES * HID / 4;
    k_zero<<<(zero_n + 255) / 256, 256>>>();
    k_deg<<<(N_EDGES + 255) / 256, 256>>>(src, dst);
    k_norm<<<(N_NODES + 255) / 256, 256>>>();
    k_gemm1<<<2048, 256>>>(x_last, W1);
    k_scatter<<<(N_EDGES * 16 + 255) / 256, 256>>>(src, dst);
    k_relu_b1<<<(N_NODES * HID + 255) / 256, 256>>>(b1);
    k_gemm2<<<2048, 256>>>(W2);
    k_scatter<<<(N_EDGES * 16 + 255) / 256, 256>>>(src, dst);
    k_layer2_post<<<2048, 256>>>(W3, b2, b3);
    k_score<<<(N_EDGES * 32 + 255) / 256, 256>>>(src_next, dst_next, W4, b4, out);
}

// round 3
// speedup vs baseline: 1.6198x; 1.6198x over previous
#include <cuda_runtime.h>

#define N_NODES 100000
#define N_EDGES 1600000
#define IN_DIM  128
#define HID     64
#define SCAN_CHUNK 1024
#define NSCAN_BLOCKS ((N_NODES + SCAN_CHUNK - 1) / SCAN_CHUNK)   // 98

// ---- scratch (static device globals; no runtime allocation) ----
__device__ float g_y [(size_t)N_NODES * HID];   // (x@W)*norm_out, reused both layers
__device__ float g_h [(size_t)N_NODES * HID];   // layer-1 activation
__device__ float g_h2[(size_t)N_NODES * HID];   // layer-2 node embedding
__device__ float g_Hs[(size_t)N_NODES * HID];   // h2 @ W3[0:64]  + b3
__device__ float g_Hd[(size_t)N_NODES * HID];   // h2 @ W3[64:128]
__device__ float g_norm_out[N_NODES];
__device__ float g_norm_in[N_NODES];
__device__ int   g_deg_out[N_NODES];
__device__ int   g_deg_in[N_NODES];
__device__ int   g_row_start[N_NODES];
__device__ int   g_cursor[N_NODES];
__device__ int   g_bsum[NSCAN_BLOCKS];
__device__ int   g_csr[N_EDGES];

// ---- 0: zero degree counters ----
__global__ void k_init() {
    int i = blockIdx.x * blockDim.x + threadIdx.x;
    if (i < N_NODES) { g_deg_out[i] = 0; g_deg_in[i] = 0; }
}

// ---- 1: degree histogram (last-timestep edges only) ----
__global__ void k_deg(const int* __restrict__ src, const int* __restrict__ dst) {
    int i = blockIdx.x * blockDim.x + threadIdx.x;
    if (i < N_EDGES) {
        atomicAdd(&g_deg_out[src[i]], 1);
        atomicAdd(&g_deg_in[dst[i]], 1);
    }
}

// ---- 2a: per-1024-chunk scan of deg_in; local-exclusive offsets + chunk totals ----
__global__ __launch_bounds__(256) void k_scan_local() {
    __shared__ int sh[256];
    int t = threadIdx.x;
    int base = blockIdx.x * SCAN_CHUNK + t * 4;
    int d0 = (base + 0 < N_NODES) ? g_deg_in[base + 0] : 0;
    int d1 = (base + 1 < N_NODES) ? g_deg_in[base + 1] : 0;
    int d2 = (base + 2 < N_NODES) ? g_deg_in[base + 2] : 0;
    int d3 = (base + 3 < N_NODES) ? g_deg_in[base + 3] : 0;
    int s = d0 + d1 + d2 + d3;
    sh[t] = s;
    __syncthreads();
    for (int off = 1; off < 256; off <<= 1) {
        int tmp = (t >= off) ? sh[t - off] : 0;
        __syncthreads();
        sh[t] += tmp;
        __syncthreads();
    }
    int excl = sh[t] - s;
    int r0 = excl, r1 = r0 + d0, r2 = r1 + d1, r3 = r2 + d2;
    if (base + 0 < N_NODES) g_row_start[base + 0] = r0;
    if (base + 1 < N_NODES) g_row_start[base + 1] = r1;
    if (base + 2 < N_NODES) g_row_start[base + 2] = r2;
    if (base + 3 < N_NODES) g_row_start[base + 3] = r3;
    if (t == 255) g_bsum[blockIdx.x] = sh[255];
}

// ---- 2b: exclusive scan of 98 chunk totals (single block) ----
__global__ void k_scan_bsums() {
    __shared__ int sh[128];
    int t = threadIdx.x;
    int v = (t < NSCAN_BLOCKS) ? g_bsum[t] : 0;
    sh[t] = v;
    __syncthreads();
    for (int off = 1; off < 128; off <<= 1) {
        int tmp = (t >= off) ? sh[t - off] : 0;
        __syncthreads();
        sh[t] += tmp;
        __syncthreads();
    }
    if (t < NSCAN_BLOCKS) g_bsum[t] = sh[t] - v;   // exclusive
}

// ---- 2c: finalize row offsets + cursors + norm factors ----
__global__ void k_scan_add() {
    int i = blockIdx.x * blockDim.x + threadIdx.x;
    if (i < N_NODES) {
        int r = g_row_start[i] + g_bsum[i >> 10];
        g_row_start[i] = r;
        g_cursor[i] = r;
        g_norm_out[i] = rsqrtf(fmaxf((float)g_deg_out[i], 1.f));
        g_norm_in[i]  = rsqrtf(fmaxf((float)g_deg_in[i],  1.f));
    }
}

// ---- 2d: fill CSR (edge -> slot in its dst row) ----
__global__ void k_csr_fill(const int* __restrict__ src, const int* __restrict__ dst) {
    int i = blockIdx.x * blockDim.x + threadIdx.x;
    if (i < N_EDGES) {
        int p = atomicAdd(&g_cursor[dst[i]], 1);
        g_csr[p] = src[i];
    }
}

// ---- 3: y = (x @ W1) * norm_out  (register-blocked: 2 nodes x 4 cols / thread) ----
__global__ __launch_bounds__(256) void k_gemm1(const float* __restrict__ x,
                                               const float* __restrict__ W1) {
    __shared__ float4 Ws[IN_DIM][16];   // 32 KB
    __shared__ float  xs[32][IN_DIM];   // 16 KB
    for (int i = threadIdx.x; i < IN_DIM * 16; i += 256)
        ((float4*)Ws)[i] = ((const float4*)W1)[i];
    const int cq = threadIdx.x & 15;
    const int np = threadIdx.x >> 4;
    for (int v0 = blockIdx.x * 32; v0 < N_NODES; v0 += gridDim.x * 32) {
        __syncthreads();
        for (int i = threadIdx.x; i < 32 * IN_DIM / 4; i += 256) {
            int n = i >> 5, c = i & 31;
            int v = v0 + n;
            ((float4*)(xs[n]))[c] = (v < N_NODES)
                ? ((const float4*)(x + (size_t)v * IN_DIM))[c]
                : make_float4(0.f, 0.f, 0.f, 0.f);
        }
        __syncthreads();
        float4 a0 = {0,0,0,0}, a1 = {0,0,0,0};
        const float* x0 = xs[2 * np];
        const float* x1 = xs[2 * np + 1];
        #pragma unroll 16
        for (int k = 0; k < IN_DIM; k++) {
            float4 w = Ws[k][cq];
            float p = x0[k], q = x1[k];
            a0.x = fmaf(p, w.x, a0.x); a0.y = fmaf(p, w.y, a0.y);
            a0.z = fmaf(p, w.z, a0.z); a0.w = fmaf(p, w.w, a0.w);
            a1.x = fmaf(q, w.x, a1.x); a1.y = fmaf(q, w.y, a1.y);
            a1.z = fmaf(q, w.z, a1.z); a1.w = fmaf(q, w.w, a1.w);
        }
        int v = v0 + 2 * np;
        if (v < N_NODES) {
            float n0 = g_norm_out[v];
            float4 o = {a0.x * n0, a0.y * n0, a0.z * n0, a0.w * n0};
            ((float4*)(g_y + (size_t)v * HID))[cq] = o;
        }
        if (v + 1 < N_NODES) {
            float n1 = g_norm_out[v + 1];
            float4 o = {a1.x * n1, a1.y * n1, a1.z * n1, a1.w * n1};
            ((float4*)(g_y + (size_t)(v + 1) * HID))[cq] = o;
        }
    }
}

// ---- 4/7: CSR gather-aggregate (warp per node). phase 0: relu -> g_h; phase 1: -> g_h2 ----
__global__ __launch_bounds__(256) void k_gather(const float* __restrict__ bias, int phase) {
    int v    = (blockIdx.x * blockDim.x + threadIdx.x) >> 5;
    int lane = threadIdx.x & 31;
    if (v >= N_NODES) return;
    float* out = phase ? g_h2 : g_h;
    int beg = g_row_start[v];
    int end = beg + g_deg_in[v];
    float a0 = 0.f, a1 = 0.f;
    int j = beg;
    for (; j + 1 < end; j += 2) {
        int s0 = g_csr[j], s1 = g_csr[j + 1];
        const float* y0 = g_y + (size_t)s0 * HID;
        const float* y1 = g_y + (size_t)s1 * HID;
        a0 += y0[lane] + y1[lane];
        a1 += y0[lane + 32] + y1[lane + 32];
    }
    if (j < end) {
        const float* y0 = g_y + (size_t)g_csr[j] * HID;
        a0 += y0[lane];
        a1 += y0[lane + 32];
    }
    float ni = g_norm_in[v];
    float v0 = a0 * ni + bias[lane];
    float v1 = a1 * ni + bias[lane + 32];
    if (phase == 0) { v0 = fmaxf(v0, 0.f); v1 = fmaxf(v1, 0.f); }
    out[(size_t)v * HID + lane]      = v0;
    out[(size_t)v * HID + lane + 32] = v1;
}

// ---- 6: y = (h @ W2) * norm_out  (register-blocked) ----
__global__ __launch_bounds__(256) void k_gemm2(const float* __restrict__ W2) {
    __shared__ float4 Ws[HID][16];      // 16 KB
    __shared__ float  hs[32][HID];      // 8 KB
    for (int i = threadIdx.x; i < HID * 16; i += 256)
        ((float4*)Ws)[i] = ((const float4*)W2)[i];
    const int cq = threadIdx.x & 15;
    const int np = threadIdx.x >> 4;
    for (int v0 = blockIdx.x * 32; v0 < N_NODES; v0 += gridDim.x * 32) {
        __syncthreads();
        for (int i = threadIdx.x; i < 32 * HID / 4; i += 256) {
            int n = i >> 4, c = i & 15;
            int v = v0 + n;
            ((float4*)(hs[n]))[c] = (v < N_NODES)
                ? ((const float4*)(g_h + (size_t)v * HID))[c]
                : make_float4(0.f, 0.f, 0.f, 0.f);
        }
        __syncthreads();
        float4 a0 = {0,0,0,0}, a1 = {0,0,0,0};
        const float* x0 = hs[2 * np];
        const float* x1 = hs[2 * np + 1];
        #pragma unroll 16
        for (int k = 0; k < HID; k++) {
            float4 w = Ws[k][cq];
            float p = x0[k], q = x1[k];
            a0.x = fmaf(p, w.x, a0.x); a0.y = fmaf(p, w.y, a0.y);
            a0.z = fmaf(p, w.z, a0.z); a0.w = fmaf(p, w.w, a0.w);
            a1.x = fmaf(q, w.x, a1.x); a1.y = fmaf(q, w.y, a1.y);
            a1.z = fmaf(q, w.z, a1.z); a1.w = fmaf(q, w.w, a1.w);
        }
        int v = v0 + 2 * np;
        if (v < N_NODES) {
            float n0 = g_norm_out[v];
            float4 o = {a0.x * n0, a0.y * n0, a0.z * n0, a0.w * n0};
            ((float4*)(g_y + (size_t)v * HID))[cq] = o;
        }
        if (v + 1 < N_NODES) {
            float n1 = g_norm_out[v + 1];
            float4 o = {a1.x * n1, a1.y * n1, a1.z * n1, a1.w * n1};
            ((float4*)(g_y + (size_t)(v + 1) * HID))[cq] = o;
        }
    }
}

// ---- 8: Hs = h2@W3[0:64] + b3 ; Hd = h2@W3[64:128]  (register-blocked) ----
__global__ __launch_bounds__(256) void k_layer2_post(const float* __restrict__ W3,
                                                     const float* __restrict__ b3v) {
    __shared__ float4 Ws[2 * HID][16];  // 32 KB
    __shared__ float  hs[32][HID];      // 8 KB
    for (int i = threadIdx.x; i < 2 * HID * 16; i += 256)
        ((float4*)Ws)[i] = ((const float4*)W3)[i];
    const int cq = threadIdx.x & 15;
    const int np = threadIdx.x >> 4;
    for (int v0 = blockIdx.x * 32; v0 < N_NODES; v0 += gridDim.x * 32) {
        __syncthreads();
        for (int i = threadIdx.x; i < 32 * HID / 4; i += 256) {
            int n = i >> 4, c = i & 15;
            int v = v0 + n;
            ((float4*)(hs[n]))[c] = (v < N_NODES)
                ? ((const float4*)(g_h2 + (size_t)v * HID))[c]
                : make_float4(0.f, 0.f, 0.f, 0.f);
        }
        __syncthreads();
        float4 s0 = {0,0,0,0}, s1 = {0,0,0,0};
        float4 d0 = {0,0,0,0}, d1 = {0,0,0,0};
        const float* x0 = hs[2 * np];
        const float* x1 = hs[2 * np + 1];
        #pragma unroll 8
        for (int k = 0; k < HID; k++) {
            float4 ws = Ws[k][cq];
            float4 wd = Ws[HID + k][cq];
            float p = x0[k], q = x1[k];
            s0.x = fmaf(p, ws.x, s0.x); s0.y = fmaf(p, ws.y, s0.y);
            s0.z = fmaf(p, ws.z, s0.z); s0.w = fmaf(p, ws.w, s0.w);
            s1.x = fmaf(q, ws.x, s1.x); s1.y = fmaf(q, ws.y, s1.y);
            s1.z = fmaf(q, ws.z, s1.z); s1.w = fmaf(q, ws.w, s1.w);
            d0.x = fmaf(p, wd.x, d0.x); d0.y = fmaf(p, wd.y, d0.y);
            d0.z = fmaf(p, wd.z, d0.z); d0.w = fmaf(p, wd.w, d0.w);
            d1.x = fmaf(q, wd.x, d1.x); d1.y = fmaf(q, wd.y, d1.y);
            d1.z = fmaf(q, wd.z, d1.z); d1.w = fmaf(q, wd.w, d1.w);
        }
        float4 b3q = ((const float4*)b3v)[cq];
        int v = v0 + 2 * np;
        if (v < N_NODES) {
            float4 os = {s0.x + b3q.x, s0.y + b3q.y, s0.z + b3q.z, s0.w + b3q.w};
            ((float4*)(g_Hs + (size_t)v * HID))[cq] = os;
            ((float4*)(g_Hd + (size_t)v * HID))[cq] = d0;
        }
        if (v + 1 < N_NODES) {
            float4 os = {s1.x + b3q.x, s1.y + b3q.y, s1.z + b3q.z, s1.w + b3q.w};
            ((float4*)(g_Hs + (size_t)(v + 1) * HID))[cq] = os;
            ((float4*)(g_Hd + (size_t)(v + 1) * HID))[cq] = d1;
        }
    }
}

// ---- 9: per-edge score (one warp per edge) ----
__global__ __launch_bounds__(256) void k_score(const int* __restrict__ sn,
                                               const int* __restrict__ dn,
                                               const float* __restrict__ W4,
                                               const float* __restrict__ b4,
                                               float* __restrict__ out) {
    int warp = (blockIdx.x * blockDim.x + threadIdx.x) >> 5;
    int lane = threadIdx.x & 31;
    if (warp >= N_EDGES) return;
    int s = __ldg(&sn[warp]);
    int d = __ldg(&dn[warp]);
    const float* hs = g_Hs + (size_t)s * HID;
    const float* hd = g_Hd + (size_t)d * HID;
    float a0 = fmaxf(hs[lane]      + hd[lane],      0.f);
    float a1 = fmaxf(hs[lane + 32] + hd[lane + 32], 0.f);
    float p  = a0 * __ldg(&W4[lane]) + a1 * __ldg(&W4[lane + 32]);
    #pragma unroll
    for (int o = 16; o; o >>= 1) p += __shfl_down_sync(0xffffffffu, p, o);
    if (lane == 0) out[warp] = p + __ldg(&b4[0]);
}

extern "C" void kernel_launch(void* const* d_in, const int* in_sizes, int n_in,
                              void* d_out, int out_size) {
    const float* feats    = (const float*)d_in[0];
    const float* W1       = (const float*)d_in[1];
    const float* b1       = (const float*)d_in[2];
    const float* W2       = (const float*)d_in[3];
    const float* b2       = (const float*)d_in[4];
    const float* W3       = (const float*)d_in[5];
    const float* b3       = (const float*)d_in[6];
    const float* W4       = (const float*)d_in[7];
    const float* b4       = (const float*)d_in[8];
    const int*   src_seq  = (const int*)d_in[9];
    const int*   dst_seq  = (const int*)d_in[10];
    const int*   src_next = (const int*)d_in[11];
    const int*   dst_next = (const int*)d_in[12];
    float* out = (float*)d_out;

    // use_temporal=False in the reference: only snapshot t = T-1 = 2 contributes.
    const float* x_last = feats   + (size_t)2 * N_NODES * IN_DIM;
    const int*   src    = src_seq + (size_t)2 * N_EDGES;
    const int*   dst    = dst_seq + (size_t)2 * N_EDGES;

    k_init<<<(N_NODES + 255) / 256, 256>>>();
    k_deg<<<(N_EDGES + 255) / 256, 256>>>(src, dst);
    k_scan_local<<<NSCAN_BLOCKS, 256>>>();
    k_scan_bsums<<<1, 128>>>();
    k_scan_add<<<(N_NODES + 255) / 256, 256>>>();
    k_csr_fill<<<(N_EDGES + 255) / 256, 256>>>(src, dst);
    k_gemm1<<<3125, 256>>>(x_last, W1);
    k_gather<<<(N_NODES * 32 + 255) / 256, 256>>>(b1, 0);
    k_gemm2<<<3125, 256>>>(W2);
    k_gather<<<(N_NODES * 32 + 255) / 256, 256>>>(b2, 1);
    k_layer2_post<<<3125, 256>>>(W3, b3);
    k_score<<<(N_EDGES * 32 + 255) / 256, 256>>>(src_next, dst_next, W4, b4, out);
}